// round 10
// baseline (speedup 1.0000x reference)
#include <cuda_runtime.h>
#include <cstdint>

#define CC    512
#define TLEN  1024
#define TT    32
#define NBLK  32
#define BATCH 32
#define JS    320             // j < JS served from smem (NRS mask rounds)
#define NRS   10              // JS / 32
#define SW_ROWS (JS + 1)      // +1 zero row for smem-segment padding
#define SW_BYTES (SW_ROWS * 128 * 4)

// Packed dual-FP32 add (Blackwell f32x2): two independent IEEE adds.
#define ADD_F32X2(out, a, b) \
    asm("add.rn.f32x2 %0, %1, %2;" : "=l"(out) : "l"(a), "l"(b))

// Scratch (no cudaMalloc allowed). Row CC (index 512) of g_WT is NEVER written:
// device globals are zero-initialized -> permanent zero row for gmem padding.
__device__ float g_WT[(CC + 1) * CC];

// ---------------------------------------------------------------------------
// Transpose rec_weight (W[i][j]) -> g_WT[j][i] so the gather is coalesced in i
// ---------------------------------------------------------------------------
__global__ void transpose_kernel(const float* __restrict__ W) {
    __shared__ float tile[32][33];
    int j0 = blockIdx.x * 32, i0 = blockIdx.y * 32;
    int tx = threadIdx.x, ty = threadIdx.y;
#pragma unroll
    for (int k = 0; k < 32; k += 8)
        tile[ty + k][tx] = W[(i0 + ty + k) * CC + (j0 + tx)];
    __syncthreads();
#pragma unroll
    for (int k = 0; k < 32; k += 8)
        g_WT[(j0 + ty + k) * CC + (i0 + tx)] = tile[tx][ty + k];
}

// ---------------------------------------------------------------------------
// R10: as R9 plus (1) gmem gather segment software-pipelined (first round's
// LDG.128s issued BEFORE the smem segment; add order still strictly ascending
// j -> value-identical) and (2) cluster barrier split arrive/wait with the
// output store + next-x prefetch inside the window.
// ---------------------------------------------------------------------------
template<int TG>
__device__ __forceinline__ void run_loop(
    int cl, int lane, int warp, int b, int i, int ctile,
    const float* __restrict__ xrow, float* __restrict__ orow,
    const float* __restrict__ sW,
    float beta, float p, float bb, float inv_p,
    int       (*s1_sm)[CC],     // [2][512] double-buffered spike times (DSMEM)
    unsigned  (*masks)[16],     // [32][16]
    int* offS_sm, int* offG_sm, int* offE_sm,   // [32] each
    short*     lst,             // [1024] compacted+padded j list
    float     (*xs_sm)[128],    // [32][128] x, then fused x+rec
    int       (*cand_sm)[128],  // [8][128]
    float*     memlast_sm,      // [128]
    float     (*pw_sm)[128],    // [33][128]: p_cl^k
    uint32_t   s1_u32base)      // smem address of s1_sm[0][0]
{
    constexpr int BASE = TG * 4;

    // beta-power table, built exactly like R1-R9 (powf with float exponent)
    float bp[BASE + 4];
#pragma unroll
    for (int k = 0; k < BASE + 4; k++) bp[k] = powf(beta, (float)k);
    float ppo[4];
#pragma unroll
    for (int u = 0; u < 4; u++) ppo[u] = powf(p, (float)(BASE + u + 1));

    float mem_last = 0.0f, a_prev = 0.0f;
    int   s1_own = -1;

    const int tid = TG * 128 + cl;
    const float* Wb  = g_WT + ctile * 128 + lane * 4;  // gmem gather base
    const float* sWb = sW + lane * 4;                  // smem gather base

    // prefetch x block 0
    float4 xv = *(const float4*)(xrow + BASE);

    for (int iter = 0; iter < NBLK; iter++) {
        // ---- phase 1: publish x slice, OR spikes into masks, adaptation ----
        xs_sm[BASE + 0][cl] = xv.x;
        xs_sm[BASE + 1][cl] = xv.y;
        xs_sm[BASE + 2][cl] = xv.z;
        xs_sm[BASE + 3][cl] = xv.w;

        float a_cur, v_init;
        if (iter > 0) {
            const int rb = (iter - 1) & 1;
            if (TG < 4) {
                int s = s1_sm[rb][tid];                // LDS (DSMEM-exchanged)
                if (s >= 0)
                    atomicOr(&masks[s][tid >> 5], 1u << (tid & 31));
            }
            v_init = (s1_own >= 0) ? 0.0f : mem_last;
            float pw_up = pw_sm[s1_own + 1][cl];       // p^(s1+1)
            float pw_dn = pw_sm[TT - 1 - s1_own][cl];  // p^(31-s1)
            float a_at  = pw_up * a_prev + inv_p;
            float new_a = a_at * pw_dn;
            a_cur  = (s1_own >= 0) ? new_a : pw_sm[TT][cl] * a_prev;
            a_prev = a_cur;
        } else {
            a_cur = 0.0f; v_init = 0.0f;               // +0 adds are identity
        }
        __syncthreads();                               // sync 1

        if (iter > 0) {
            // ---- warp 0: counts + scan only (extraction is parallel) ----
            if (TG == 0 && warp == 0) {
                int cntS = 0, cntG = 0;
#pragma unroll
                for (int r = 0; r < NRS; r++)  cntS += __popc(masks[lane][r]);
#pragma unroll
                for (int r = NRS; r < 16; r++) cntG += __popc(masks[lane][r]);
                int pS = (cntS + 7) & ~7;
                int pG = (cntG + 7) & ~7;
                int pt = pS + pG;
                int sc = pt;
#pragma unroll
                for (int d = 1; d < 32; d <<= 1) {
                    int o = __shfl_up_sync(0xffffffffu, sc, d);
                    if (lane >= d) sc += o;
                }
                int excl = sc - pt;
                offS_sm[lane] = excl;
                offG_sm[lane] = excl + pS;
                offE_sm[lane] = excl + pt;
            }
            __syncthreads();                           // sync 2

            // ---- parallel extraction: warp = bucket t, lane = mask round ----
            {
                const int t = warp;
                unsigned mr = (lane < 16) ? masks[t][lane] : 0u;
                int c  = __popc(mr);
                int cS = (lane < NRS) ? c : 0;
                int cG = (lane >= NRS && lane < 16) ? c : 0;
                int sS = cS, sG = cG;
#pragma unroll
                for (int d = 1; d < 32; d <<= 1) {
                    int oS = __shfl_up_sync(0xffffffffu, sS, d);
                    int oG = __shfl_up_sync(0xffffffffu, sG, d);
                    if (lane >= d) { sS += oS; sG += oG; }
                }
                int totS = __shfl_sync(0xffffffffu, sS, 31);
                int totG = __shfl_sync(0xffffffffu, sG, 31);
                int exS = sS - cS, exG = sG - cG;
                int offS = offS_sm[t], offG = offG_sm[t], offE = offE_sm[t];
                int pos = (lane < NRS) ? (offS + exS) : (offG + exG);
                const int jb = lane * 32;
                while (mr) {                           // asc bit within round
                    int j = jb + __ffs(mr) - 1;
                    mr &= mr - 1;
                    lst[pos++] = (short)j;
                }
                int padS = offG - (offS + totS);       // <= 7
                if (lane < padS) lst[offS + totS + lane] = (short)JS;
                int padG = offE - (offG + totG);       // <= 7
                if (lane < padG) lst[offG + totG + lane] = (short)CC;
            }
            __syncthreads();                           // sync 3

            // ---- gather: warp = bucket t, lane = 4 channels.
            //      First gmem round's loads issued EARLY (latency overlaps the
            //      smem segment); add order strictly ascending j: all smem
            //      adds, then gmem adds round-by-round -> value-identical. ----
            {
                const int t = warp;
                unsigned long long a01 = 0ull, a23 = 0ull;
                int kS = offS_sm[t]; const int eS = offG_sm[t];
                int kG = offG_sm[t]; const int eG = offE_sm[t];

                // early-issue first gmem round (warp-uniform predicate)
                ulonglong2 g0, g1, g2, g3, g4, g5, g6, g7;
                bool haveG = kG < eG;
                if (haveG) {
                    uint4 q = *(const uint4*)(lst + kG);
                    g0 = *(const ulonglong2*)(Wb + (q.x & 0xffffu) * CC);
                    g1 = *(const ulonglong2*)(Wb + (q.x >> 16)     * CC);
                    g2 = *(const ulonglong2*)(Wb + (q.y & 0xffffu) * CC);
                    g3 = *(const ulonglong2*)(Wb + (q.y >> 16)     * CC);
                    g4 = *(const ulonglong2*)(Wb + (q.z & 0xffffu) * CC);
                    g5 = *(const ulonglong2*)(Wb + (q.z >> 16)     * CC);
                    g6 = *(const ulonglong2*)(Wb + (q.w & 0xffffu) * CC);
                    g7 = *(const ulonglong2*)(Wb + (q.w >> 16)     * CC);
                }

                // smem segment
#pragma unroll 1
                while (kS < eS) {                      // uniform, len % 8 == 0
                    uint4 q = *(const uint4*)(lst + kS);
                    ulonglong2 w0 = *(const ulonglong2*)(sWb + (q.x & 0xffffu) * 128);
                    ulonglong2 w1 = *(const ulonglong2*)(sWb + (q.x >> 16)     * 128);
                    ulonglong2 w2 = *(const ulonglong2*)(sWb + (q.y & 0xffffu) * 128);
                    ulonglong2 w3 = *(const ulonglong2*)(sWb + (q.y >> 16)     * 128);
                    ulonglong2 w4 = *(const ulonglong2*)(sWb + (q.z & 0xffffu) * 128);
                    ulonglong2 w5 = *(const ulonglong2*)(sWb + (q.z >> 16)     * 128);
                    ulonglong2 w6 = *(const ulonglong2*)(sWb + (q.w & 0xffffu) * 128);
                    ulonglong2 w7 = *(const ulonglong2*)(sWb + (q.w >> 16)     * 128);
                    ADD_F32X2(a01, a01, w0.x); ADD_F32X2(a23, a23, w0.y);
                    ADD_F32X2(a01, a01, w1.x); ADD_F32X2(a23, a23, w1.y);
                    ADD_F32X2(a01, a01, w2.x); ADD_F32X2(a23, a23, w2.y);
                    ADD_F32X2(a01, a01, w3.x); ADD_F32X2(a23, a23, w3.y);
                    ADD_F32X2(a01, a01, w4.x); ADD_F32X2(a23, a23, w4.y);
                    ADD_F32X2(a01, a01, w5.x); ADD_F32X2(a23, a23, w5.y);
                    ADD_F32X2(a01, a01, w6.x); ADD_F32X2(a23, a23, w6.y);
                    ADD_F32X2(a01, a01, w7.x); ADD_F32X2(a23, a23, w7.y);
                    kS += 8;
                }

                // gmem segment: consume buffered round, then refill
#pragma unroll 1
                while (haveG) {
                    ADD_F32X2(a01, a01, g0.x); ADD_F32X2(a23, a23, g0.y);
                    ADD_F32X2(a01, a01, g1.x); ADD_F32X2(a23, a23, g1.y);
                    ADD_F32X2(a01, a01, g2.x); ADD_F32X2(a23, a23, g2.y);
                    ADD_F32X2(a01, a01, g3.x); ADD_F32X2(a23, a23, g3.y);
                    ADD_F32X2(a01, a01, g4.x); ADD_F32X2(a23, a23, g4.y);
                    ADD_F32X2(a01, a01, g5.x); ADD_F32X2(a23, a23, g5.y);
                    ADD_F32X2(a01, a01, g6.x); ADD_F32X2(a23, a23, g6.y);
                    ADD_F32X2(a01, a01, g7.x); ADD_F32X2(a23, a23, g7.y);
                    kG += 8;
                    haveG = kG < eG;
                    if (haveG) {
                        uint4 q = *(const uint4*)(lst + kG);
                        g0 = *(const ulonglong2*)(Wb + (q.x & 0xffffu) * CC);
                        g1 = *(const ulonglong2*)(Wb + (q.x >> 16)     * CC);
                        g2 = *(const ulonglong2*)(Wb + (q.y & 0xffffu) * CC);
                        g3 = *(const ulonglong2*)(Wb + (q.y >> 16)     * CC);
                        g4 = *(const ulonglong2*)(Wb + (q.z & 0xffffu) * CC);
                        g5 = *(const ulonglong2*)(Wb + (q.z >> 16)     * CC);
                        g6 = *(const ulonglong2*)(Wb + (q.w & 0xffffu) * CC);
                        g7 = *(const ulonglong2*)(Wb + (q.w >> 16)     * CC);
                    }
                }

                // cur = x + rec (x first operand, as R8/R9)
                ulonglong2 xv2 = *(const ulonglong2*)(&xs_sm[t][lane * 4]);
                ADD_F32X2(a01, xv2.x, a01);
                ADD_F32X2(a23, xv2.y, a23);
                ulonglong2 st2; st2.x = a01; st2.y = a23;
                *(ulonglong2*)(&xs_sm[t][lane * 4]) = st2;

                // zero masks for the NEXT iteration (read finished at sync 3)
                if (TG >= 4) ((unsigned*)masks)[tid - 512] = 0;
            }
        }
        __syncthreads();                               // sync 4

        // ---- membrane: on-the-fly fixups, exact ascending-s fmaf chains ----
        float m[4] = {0.0f, 0.0f, 0.0f, 0.0f};
        const float bv = beta * v_init;                // +0 when not applicable
#pragma unroll
        for (int s = 0; s < BASE + 4; s++) {
            float val = xs_sm[s][cl];
            if (s < s1_own) val = 0.0f;                // zero before prev spike
            if (s == 0)     val += bv;                 // beta*v_init at t=0
#pragma unroll
            for (int u = 0; u < 4; u++)
                if (s <= BASE + u)
                    m[u] = fmaf(bp[BASE + u - s], val, m[u]);
        }
        int cand = 64;
#pragma unroll
        for (int u = 0; u < 4; u++) {
            float vth = 1.0f + bb * (ppo[u] * a_cur);
            if (((m[u] - vth) > 0.0f) && cand == 64) cand = BASE + u;
        }
        cand_sm[TG][cl] = cand;
        if (TG == 7) memlast_sm[cl] = m[3];
        __syncthreads();                               // sync 5

        // ---- combine: first crossing over all 8 t-groups; mem[31] ----
        int s1n = min(min(min(cand_sm[0][cl], cand_sm[1][cl]),
                          min(cand_sm[2][cl], cand_sm[3][cl])),
                      min(min(cand_sm[4][cl], cand_sm[5][cl]),
                          min(cand_sm[6][cl], cand_sm[7][cl])));
        int s1_new = (s1n == 64) ? -1 : s1n;
        mem_last = memlast_sm[cl];
        s1_own   = s1_new;

        // spike vector (pure function of s1_new)
        float4 v;
        v.x = (BASE + 0 == s1_new) ? 1.0f : 0.0f;
        v.y = (BASE + 1 == s1_new) ? 1.0f : 0.0f;
        v.z = (BASE + 2 == s1_new) ? 1.0f : 0.0f;
        v.w = (BASE + 3 == s1_new) ? 1.0f : 0.0f;

        if (iter < NBLK - 1) {
            // ---- publish DSMEM, arrive (release), fill the barrier window
            //      with the output store + next-x prefetch, then wait ----
            if (TG == 0) {
                uint32_t loc = s1_u32base +
                               (uint32_t)(((iter & 1) * CC + i) * sizeof(int));
#pragma unroll
                for (int rk = 0; rk < 4; rk++) {
                    uint32_t rem;
                    asm volatile("mapa.shared::cluster.u32 %0, %1, %2;"
                                 : "=r"(rem) : "r"(loc), "r"(rk));
                    asm volatile("st.shared::cluster.u32 [%0], %1;"
                                 :: "r"(rem), "r"(s1_new) : "memory");
                }
            }
            asm volatile("barrier.cluster.arrive.aligned;" ::: "memory");
            *(float4*)(orow + iter * TT + BASE) = v;
            xv = *(const float4*)(xrow + (iter + 1) * TT + BASE);
            asm volatile("barrier.cluster.wait.aligned;"   ::: "memory");
        } else {
            *(float4*)(orow + iter * TT + BASE) = v;
        }
    }
}

__global__ void __cluster_dims__(4, 1, 1) __launch_bounds__(1024, 1)
snn_kernel(const float* __restrict__ x,
           const float* __restrict__ beta_raw,
           const float* __restrict__ p_raw,
           const float* __restrict__ b_raw,
           float* __restrict__ out)
{
    extern __shared__ __align__(16) float sW[];   // [SW_ROWS][128]

    const int tid  = threadIdx.x;
    const int b    = blockIdx.x >> 2;
    if (b >= BATCH) return;                 // padding clusters exit whole
    const int ctile = blockIdx.x & 3;
    const int cl   = tid & 127;             // channel-local
    const int tg   = tid >> 7;              // t-group (0..7)
    const int lane = tid & 31, warp = tid >> 5;
    const int i    = ctile * 128 + cl;      // channel

    float beta = beta_raw[i];
    beta = fminf(fmaxf(beta, 0.001f), 0.999f);
    float p  = fminf(fabsf(p_raw[i]), 0.999f);
    float bb = fminf(fmaxf(fabsf(b_raw[i]), 0.001f), 1.0f);
    const float inv_p = 1.0f / p;

    __shared__ int                 s1_sm[2][CC];
    __shared__ unsigned            masks[TT][16];
    __shared__ int                 offS_sm[TT], offG_sm[TT], offE_sm[TT];
    __shared__ __align__(16) short lst[1024];
    __shared__ __align__(16) float xs_sm[TT][128];
    __shared__ int                 cand_sm[8][128];
    __shared__ float               memlast_sm[128];
    __shared__ float               pw_sm[TT + 1][128];   // p_cl^k, k=0..32

    uint32_t s1_u32base;
    asm("{ .reg .u64 t0; cvta.to.shared.u64 t0, %1; cvt.u32.u64 %0, t0; }"
        : "=r"(s1_u32base) : "l"(&s1_sm[0][0]));

    // ---- init: smem W slice (rows j<JS), zero row, masks zero, pw table ----
#pragma unroll 1
    for (int k = tid; k < JS * 32; k += 1024) {          // 32 float4 per row
        int j = k >> 5, c4 = k & 31;
        ((float4*)sW)[k] = *(const float4*)(g_WT + (size_t)j * CC + ctile * 128 + c4 * 4);
    }
    if (tid < 32)                                        // zero row JS
        ((float4*)(sW + JS * 128))[tid] = make_float4(0.f, 0.f, 0.f, 0.f);
    if (tid < TT * 16)
        ((unsigned*)masks)[tid] = 0;                     // first-use zeroing
#pragma unroll 1
    for (int k = tid; k < (TT + 1) * 128; k += 1024) {
        int ke = k >> 7, c0 = k & 127;
        float pc = fminf(fabsf(p_raw[ctile * 128 + c0]), 0.999f);
        pw_sm[ke][c0] = powf(pc, (float)ke);
    }
    __syncthreads();

    const float* xrow = x   + (size_t)(b * CC + i) * TLEN;
    float*       orow = out + (size_t)(b * CC + i) * TLEN;

    switch (tg) {
    case 0: run_loop<0>(cl, lane, warp, b, i, ctile, xrow, orow, sW, beta, p, bb, inv_p,
                        s1_sm, masks, offS_sm, offG_sm, offE_sm, lst, xs_sm, cand_sm, memlast_sm, pw_sm, s1_u32base); break;
    case 1: run_loop<1>(cl, lane, warp, b, i, ctile, xrow, orow, sW, beta, p, bb, inv_p,
                        s1_sm, masks, offS_sm, offG_sm, offE_sm, lst, xs_sm, cand_sm, memlast_sm, pw_sm, s1_u32base); break;
    case 2: run_loop<2>(cl, lane, warp, b, i, ctile, xrow, orow, sW, beta, p, bb, inv_p,
                        s1_sm, masks, offS_sm, offG_sm, offE_sm, lst, xs_sm, cand_sm, memlast_sm, pw_sm, s1_u32base); break;
    case 3: run_loop<3>(cl, lane, warp, b, i, ctile, xrow, orow, sW, beta, p, bb, inv_p,
                        s1_sm, masks, offS_sm, offG_sm, offE_sm, lst, xs_sm, cand_sm, memlast_sm, pw_sm, s1_u32base); break;
    case 4: run_loop<4>(cl, lane, warp, b, i, ctile, xrow, orow, sW, beta, p, bb, inv_p,
                        s1_sm, masks, offS_sm, offG_sm, offE_sm, lst, xs_sm, cand_sm, memlast_sm, pw_sm, s1_u32base); break;
    case 5: run_loop<5>(cl, lane, warp, b, i, ctile, xrow, orow, sW, beta, p, bb, inv_p,
                        s1_sm, masks, offS_sm, offG_sm, offE_sm, lst, xs_sm, cand_sm, memlast_sm, pw_sm, s1_u32base); break;
    case 6: run_loop<6>(cl, lane, warp, b, i, ctile, xrow, orow, sW, beta, p, bb, inv_p,
                        s1_sm, masks, offS_sm, offG_sm, offE_sm, lst, xs_sm, cand_sm, memlast_sm, pw_sm, s1_u32base); break;
    default: run_loop<7>(cl, lane, warp, b, i, ctile, xrow, orow, sW, beta, p, bb, inv_p,
                        s1_sm, masks, offS_sm, offG_sm, offE_sm, lst, xs_sm, cand_sm, memlast_sm, pw_sm, s1_u32base); break;
    }
}

// ---------------------------------------------------------------------------
extern "C" void kernel_launch(void* const* d_in, const int* in_sizes, int n_in,
                              void* d_out, int out_size)
{
    const float* x        = (const float*)d_in[0];
    const float* beta_raw = (const float*)d_in[1];
    const float* rec_w    = (const float*)d_in[2];
    const float* p_raw    = (const float*)d_in[3];
    const float* b_raw    = (const float*)d_in[4];
    float* out = (float*)d_out;

    // opt-in to large dynamic smem (host-side attribute, not an allocation)
    static bool attr_set = false;
    if (!attr_set) {
        cudaFuncSetAttribute(snn_kernel,
                             cudaFuncAttributeMaxDynamicSharedMemorySize,
                             SW_BYTES);
        attr_set = true;
    }

    transpose_kernel<<<dim3(16, 16), dim3(32, 8)>>>(rec_w);
    // 148 CTAs (37 clusters of 4): clusters with b>=32 exit immediately
    snn_kernel<<<148, 1024, SW_BYTES>>>(x, beta_raw, p_raw, b_raw, out);
}

// round 11
// speedup vs baseline: 1.2086x; 1.2086x over previous
#include <cuda_runtime.h>
#include <cstdint>

#define CC    512
#define TLEN  1024
#define TT    32
#define NBLK  32
#define BATCH 32
#define JS    352             // j < JS served from smem (NRS mask rounds)
#define NRS   11              // JS / 32
#define SW_ROWS (JS + 1)      // +1 zero row for smem-segment padding
#define SW_BYTES (SW_ROWS * 128 * 4)

// Packed dual-FP32 add (Blackwell f32x2): two independent IEEE adds.
#define ADD_F32X2(out, a, b) \
    asm("add.rn.f32x2 %0, %1, %2;" : "=l"(out) : "l"(a), "l"(b))

// Scratch (no cudaMalloc allowed). Row CC (index 512) of g_WT is NEVER written:
// device globals are zero-initialized -> permanent zero row for gmem padding.
__device__ float g_WT[(CC + 1) * CC];

// ---------------------------------------------------------------------------
// Transpose rec_weight (W[i][j]) -> g_WT[j][i] so the gather is coalesced in i
// ---------------------------------------------------------------------------
__global__ void transpose_kernel(const float* __restrict__ W) {
    __shared__ float tile[32][33];
    int j0 = blockIdx.x * 32, i0 = blockIdx.y * 32;
    int tx = threadIdx.x, ty = threadIdx.y;
#pragma unroll
    for (int k = 0; k < 32; k += 8)
        tile[ty + k][tx] = W[(i0 + ty + k) * CC + (j0 + tx)];
    __syncthreads();
#pragma unroll
    for (int k = 0; k < 32; k += 8)
        g_WT[(j0 + ty + k) * CC + (i0 + tx)] = tile[tx][ty + k];
}

// ---------------------------------------------------------------------------
// R11 = R9 gather (no early-issue pipelining -- it spilled at the 64-reg cap)
// + split cluster barrier (STG out + next-x LDG inside arrive/wait window)
// + JS raised 320 -> 352. Bitwise-identical spike decisions.
// ---------------------------------------------------------------------------
template<int TG>
__device__ __forceinline__ void run_loop(
    int cl, int lane, int warp, int b, int i, int ctile,
    const float* __restrict__ xrow, float* __restrict__ orow,
    const float* __restrict__ sW,
    float beta, float p, float bb, float inv_p,
    int       (*s1_sm)[CC],     // [2][512] double-buffered spike times (DSMEM)
    unsigned  (*masks)[16],     // [32][16]
    int* offS_sm, int* offG_sm, int* offE_sm,   // [32] each
    short*     lst,             // [1024] compacted+padded j list
    float     (*xs_sm)[128],    // [32][128] x, then fused x+rec
    int       (*cand_sm)[128],  // [8][128]
    float*     memlast_sm,      // [128]
    float     (*pw_sm)[128],    // [33][128]: p_cl^k
    uint32_t   s1_u32base)      // smem address of s1_sm[0][0]
{
    constexpr int BASE = TG * 4;

    // beta-power table, built exactly like R1-R10 (powf with float exponent)
    float bp[BASE + 4];
#pragma unroll
    for (int k = 0; k < BASE + 4; k++) bp[k] = powf(beta, (float)k);
    float ppo[4];
#pragma unroll
    for (int u = 0; u < 4; u++) ppo[u] = powf(p, (float)(BASE + u + 1));

    float mem_last = 0.0f, a_prev = 0.0f;
    int   s1_own = -1;

    const int tid = TG * 128 + cl;
    const float* Wb  = g_WT + ctile * 128 + lane * 4;  // gmem gather base
    const float* sWb = sW + lane * 4;                  // smem gather base

    // prefetch x block 0
    float4 xv = *(const float4*)(xrow + BASE);

    for (int iter = 0; iter < NBLK; iter++) {
        // ---- phase 1: publish x slice, OR spikes into masks, adaptation ----
        xs_sm[BASE + 0][cl] = xv.x;
        xs_sm[BASE + 1][cl] = xv.y;
        xs_sm[BASE + 2][cl] = xv.z;
        xs_sm[BASE + 3][cl] = xv.w;

        float a_cur, v_init;
        if (iter > 0) {
            const int rb = (iter - 1) & 1;
            if (TG < 4) {
                int s = s1_sm[rb][tid];                // LDS (DSMEM-exchanged)
                if (s >= 0)
                    atomicOr(&masks[s][tid >> 5], 1u << (tid & 31));
            }
            v_init = (s1_own >= 0) ? 0.0f : mem_last;
            float pw_up = pw_sm[s1_own + 1][cl];       // p^(s1+1)
            float pw_dn = pw_sm[TT - 1 - s1_own][cl];  // p^(31-s1)
            float a_at  = pw_up * a_prev + inv_p;
            float new_a = a_at * pw_dn;
            a_cur  = (s1_own >= 0) ? new_a : pw_sm[TT][cl] * a_prev;
            a_prev = a_cur;
        } else {
            a_cur = 0.0f; v_init = 0.0f;               // +0 adds are identity
        }
        __syncthreads();                               // sync 1

        if (iter > 0) {
            // ---- warp 0: counts + scan only (extraction is parallel) ----
            if (TG == 0 && warp == 0) {
                int cntS = 0, cntG = 0;
#pragma unroll
                for (int r = 0; r < NRS; r++)  cntS += __popc(masks[lane][r]);
#pragma unroll
                for (int r = NRS; r < 16; r++) cntG += __popc(masks[lane][r]);
                int pS = (cntS + 7) & ~7;
                int pG = (cntG + 7) & ~7;
                int pt = pS + pG;
                int sc = pt;
#pragma unroll
                for (int d = 1; d < 32; d <<= 1) {
                    int o = __shfl_up_sync(0xffffffffu, sc, d);
                    if (lane >= d) sc += o;
                }
                int excl = sc - pt;
                offS_sm[lane] = excl;
                offG_sm[lane] = excl + pS;
                offE_sm[lane] = excl + pt;
            }
            __syncthreads();                           // sync 2

            // ---- parallel extraction: warp = bucket t, lane = mask round ----
            {
                const int t = warp;
                unsigned mr = (lane < 16) ? masks[t][lane] : 0u;
                int c  = __popc(mr);
                int cS = (lane < NRS) ? c : 0;
                int cG = (lane >= NRS && lane < 16) ? c : 0;
                int sS = cS, sG = cG;
#pragma unroll
                for (int d = 1; d < 32; d <<= 1) {
                    int oS = __shfl_up_sync(0xffffffffu, sS, d);
                    int oG = __shfl_up_sync(0xffffffffu, sG, d);
                    if (lane >= d) { sS += oS; sG += oG; }
                }
                int totS = __shfl_sync(0xffffffffu, sS, 31);
                int totG = __shfl_sync(0xffffffffu, sG, 31);
                int exS = sS - cS, exG = sG - cG;
                int offS = offS_sm[t], offG = offG_sm[t], offE = offE_sm[t];
                int pos = (lane < NRS) ? (offS + exS) : (offG + exG);
                const int jb = lane * 32;
                while (mr) {                           // asc bit within round
                    int j = jb + __ffs(mr) - 1;
                    mr &= mr - 1;
                    lst[pos++] = (short)j;
                }
                int padS = offG - (offS + totS);       // <= 7
                if (lane < padS) lst[offS + totS + lane] = (short)JS;
                int padG = offE - (offG + totG);       // <= 7
                if (lane < padG) lst[offG + totG + lane] = (short)CC;
            }
            __syncthreads();                           // sync 3

            // ---- gather: warp = bucket t, lane = 4 channels; smem then gmem
            //      segment, ascending-j f32x2 chains + exact zeros; finally
            //      fuse x: cur = x + rec (single FADD, commutes bitwise). ----
            {
                const int t = warp;
                unsigned long long a01 = 0ull, a23 = 0ull;
                int k = offS_sm[t]; const int eS = offG_sm[t];
#pragma unroll 1
                while (k < eS) {                       // uniform, len % 8 == 0
                    uint4 q = *(const uint4*)(lst + k);
                    ulonglong2 w0 = *(const ulonglong2*)(sWb + (q.x & 0xffffu) * 128);
                    ulonglong2 w1 = *(const ulonglong2*)(sWb + (q.x >> 16)     * 128);
                    ulonglong2 w2 = *(const ulonglong2*)(sWb + (q.y & 0xffffu) * 128);
                    ulonglong2 w3 = *(const ulonglong2*)(sWb + (q.y >> 16)     * 128);
                    ulonglong2 w4 = *(const ulonglong2*)(sWb + (q.z & 0xffffu) * 128);
                    ulonglong2 w5 = *(const ulonglong2*)(sWb + (q.z >> 16)     * 128);
                    ulonglong2 w6 = *(const ulonglong2*)(sWb + (q.w & 0xffffu) * 128);
                    ulonglong2 w7 = *(const ulonglong2*)(sWb + (q.w >> 16)     * 128);
                    ADD_F32X2(a01, a01, w0.x); ADD_F32X2(a23, a23, w0.y);
                    ADD_F32X2(a01, a01, w1.x); ADD_F32X2(a23, a23, w1.y);
                    ADD_F32X2(a01, a01, w2.x); ADD_F32X2(a23, a23, w2.y);
                    ADD_F32X2(a01, a01, w3.x); ADD_F32X2(a23, a23, w3.y);
                    ADD_F32X2(a01, a01, w4.x); ADD_F32X2(a23, a23, w4.y);
                    ADD_F32X2(a01, a01, w5.x); ADD_F32X2(a23, a23, w5.y);
                    ADD_F32X2(a01, a01, w6.x); ADD_F32X2(a23, a23, w6.y);
                    ADD_F32X2(a01, a01, w7.x); ADD_F32X2(a23, a23, w7.y);
                    k += 8;
                }
                k = offG_sm[t]; const int eG = offE_sm[t];
#pragma unroll 1
                while (k < eG) {
                    uint4 q = *(const uint4*)(lst + k);
                    ulonglong2 w0 = *(const ulonglong2*)(Wb + (q.x & 0xffffu) * CC);
                    ulonglong2 w1 = *(const ulonglong2*)(Wb + (q.x >> 16)     * CC);
                    ulonglong2 w2 = *(const ulonglong2*)(Wb + (q.y & 0xffffu) * CC);
                    ulonglong2 w3 = *(const ulonglong2*)(Wb + (q.y >> 16)     * CC);
                    ulonglong2 w4 = *(const ulonglong2*)(Wb + (q.z & 0xffffu) * CC);
                    ulonglong2 w5 = *(const ulonglong2*)(Wb + (q.z >> 16)     * CC);
                    ulonglong2 w6 = *(const ulonglong2*)(Wb + (q.w & 0xffffu) * CC);
                    ulonglong2 w7 = *(const ulonglong2*)(Wb + (q.w >> 16)     * CC);
                    ADD_F32X2(a01, a01, w0.x); ADD_F32X2(a23, a23, w0.y);
                    ADD_F32X2(a01, a01, w1.x); ADD_F32X2(a23, a23, w1.y);
                    ADD_F32X2(a01, a01, w2.x); ADD_F32X2(a23, a23, w2.y);
                    ADD_F32X2(a01, a01, w3.x); ADD_F32X2(a23, a23, w3.y);
                    ADD_F32X2(a01, a01, w4.x); ADD_F32X2(a23, a23, w4.y);
                    ADD_F32X2(a01, a01, w5.x); ADD_F32X2(a23, a23, w5.y);
                    ADD_F32X2(a01, a01, w6.x); ADD_F32X2(a23, a23, w6.y);
                    ADD_F32X2(a01, a01, w7.x); ADD_F32X2(a23, a23, w7.y);
                    k += 8;
                }
                // cur = x + rec (x first operand, as R8/R9)
                ulonglong2 xv2 = *(const ulonglong2*)(&xs_sm[t][lane * 4]);
                ADD_F32X2(a01, xv2.x, a01);
                ADD_F32X2(a23, xv2.y, a23);
                ulonglong2 st2; st2.x = a01; st2.y = a23;
                *(ulonglong2*)(&xs_sm[t][lane * 4]) = st2;

                // zero masks for the NEXT iteration (read finished at sync 3)
                if (TG >= 4) ((unsigned*)masks)[tid - 512] = 0;
            }
        }
        __syncthreads();                               // sync 4

        // ---- membrane: on-the-fly fixups, exact ascending-s fmaf chains ----
        float m[4] = {0.0f, 0.0f, 0.0f, 0.0f};
        const float bv = beta * v_init;                // +0 when not applicable
#pragma unroll
        for (int s = 0; s < BASE + 4; s++) {
            float val = xs_sm[s][cl];
            if (s < s1_own) val = 0.0f;                // zero before prev spike
            if (s == 0)     val += bv;                 // beta*v_init at t=0
#pragma unroll
            for (int u = 0; u < 4; u++)
                if (s <= BASE + u)
                    m[u] = fmaf(bp[BASE + u - s], val, m[u]);
        }
        int cand = 64;
#pragma unroll
        for (int u = 0; u < 4; u++) {
            float vth = 1.0f + bb * (ppo[u] * a_cur);
            if (((m[u] - vth) > 0.0f) && cand == 64) cand = BASE + u;
        }
        cand_sm[TG][cl] = cand;
        if (TG == 7) memlast_sm[cl] = m[3];
        __syncthreads();                               // sync 5

        // ---- combine: first crossing over all 8 t-groups; mem[31] ----
        int s1n = min(min(min(cand_sm[0][cl], cand_sm[1][cl]),
                          min(cand_sm[2][cl], cand_sm[3][cl])),
                      min(min(cand_sm[4][cl], cand_sm[5][cl]),
                          min(cand_sm[6][cl], cand_sm[7][cl])));
        int s1_new = (s1n == 64) ? -1 : s1n;
        mem_last = memlast_sm[cl];
        s1_own   = s1_new;

        // spike vector (pure function of s1_new)
        float4 v;
        v.x = (BASE + 0 == s1_new) ? 1.0f : 0.0f;
        v.y = (BASE + 1 == s1_new) ? 1.0f : 0.0f;
        v.z = (BASE + 2 == s1_new) ? 1.0f : 0.0f;
        v.w = (BASE + 3 == s1_new) ? 1.0f : 0.0f;

        if (iter < NBLK - 1) {
            // ---- publish DSMEM, arrive (release), fill the barrier window
            //      with the output store + next-x prefetch, then wait ----
            if (TG == 0) {
                uint32_t loc = s1_u32base +
                               (uint32_t)(((iter & 1) * CC + i) * sizeof(int));
#pragma unroll
                for (int rk = 0; rk < 4; rk++) {
                    uint32_t rem;
                    asm volatile("mapa.shared::cluster.u32 %0, %1, %2;"
                                 : "=r"(rem) : "r"(loc), "r"(rk));
                    asm volatile("st.shared::cluster.u32 [%0], %1;"
                                 :: "r"(rem), "r"(s1_new) : "memory");
                }
            }
            asm volatile("barrier.cluster.arrive.aligned;" ::: "memory");
            *(float4*)(orow + iter * TT + BASE) = v;
            xv = *(const float4*)(xrow + (iter + 1) * TT + BASE);
            asm volatile("barrier.cluster.wait.aligned;"   ::: "memory");
        } else {
            *(float4*)(orow + iter * TT + BASE) = v;
        }
    }
}

__global__ void __cluster_dims__(4, 1, 1) __launch_bounds__(1024, 1)
snn_kernel(const float* __restrict__ x,
           const float* __restrict__ beta_raw,
           const float* __restrict__ p_raw,
           const float* __restrict__ b_raw,
           float* __restrict__ out)
{
    extern __shared__ __align__(16) float sW[];   // [SW_ROWS][128]

    const int tid  = threadIdx.x;
    const int b    = blockIdx.x >> 2;
    if (b >= BATCH) return;                 // padding clusters exit whole
    const int ctile = blockIdx.x & 3;
    const int cl   = tid & 127;             // channel-local
    const int tg   = tid >> 7;              // t-group (0..7)
    const int lane = tid & 31, warp = tid >> 5;
    const int i    = ctile * 128 + cl;      // channel

    float beta = beta_raw[i];
    beta = fminf(fmaxf(beta, 0.001f), 0.999f);
    float p  = fminf(fabsf(p_raw[i]), 0.999f);
    float bb = fminf(fmaxf(fabsf(b_raw[i]), 0.001f), 1.0f);
    const float inv_p = 1.0f / p;

    __shared__ int                 s1_sm[2][CC];
    __shared__ unsigned            masks[TT][16];
    __shared__ int                 offS_sm[TT], offG_sm[TT], offE_sm[TT];
    __shared__ __align__(16) short lst[1024];
    __shared__ __align__(16) float xs_sm[TT][128];
    __shared__ int                 cand_sm[8][128];
    __shared__ float               memlast_sm[128];
    __shared__ float               pw_sm[TT + 1][128];   // p_cl^k, k=0..32

    uint32_t s1_u32base;
    asm("{ .reg .u64 t0; cvta.to.shared.u64 t0, %1; cvt.u32.u64 %0, t0; }"
        : "=r"(s1_u32base) : "l"(&s1_sm[0][0]));

    // ---- init: smem W slice (rows j<JS), zero row, masks zero, pw table ----
#pragma unroll 1
    for (int k = tid; k < JS * 32; k += 1024) {          // 32 float4 per row
        int j = k >> 5, c4 = k & 31;
        ((float4*)sW)[k] = *(const float4*)(g_WT + (size_t)j * CC + ctile * 128 + c4 * 4);
    }
    if (tid < 32)                                        // zero row JS
        ((float4*)(sW + JS * 128))[tid] = make_float4(0.f, 0.f, 0.f, 0.f);
    if (tid < TT * 16)
        ((unsigned*)masks)[tid] = 0;                     // first-use zeroing
#pragma unroll 1
    for (int k = tid; k < (TT + 1) * 128; k += 1024) {
        int ke = k >> 7, c0 = k & 127;
        float pc = fminf(fabsf(p_raw[ctile * 128 + c0]), 0.999f);
        pw_sm[ke][c0] = powf(pc, (float)ke);
    }
    __syncthreads();

    const float* xrow = x   + (size_t)(b * CC + i) * TLEN;
    float*       orow = out + (size_t)(b * CC + i) * TLEN;

    switch (tg) {
    case 0: run_loop<0>(cl, lane, warp, b, i, ctile, xrow, orow, sW, beta, p, bb, inv_p,
                        s1_sm, masks, offS_sm, offG_sm, offE_sm, lst, xs_sm, cand_sm, memlast_sm, pw_sm, s1_u32base); break;
    case 1: run_loop<1>(cl, lane, warp, b, i, ctile, xrow, orow, sW, beta, p, bb, inv_p,
                        s1_sm, masks, offS_sm, offG_sm, offE_sm, lst, xs_sm, cand_sm, memlast_sm, pw_sm, s1_u32base); break;
    case 2: run_loop<2>(cl, lane, warp, b, i, ctile, xrow, orow, sW, beta, p, bb, inv_p,
                        s1_sm, masks, offS_sm, offG_sm, offE_sm, lst, xs_sm, cand_sm, memlast_sm, pw_sm, s1_u32base); break;
    case 3: run_loop<3>(cl, lane, warp, b, i, ctile, xrow, orow, sW, beta, p, bb, inv_p,
                        s1_sm, masks, offS_sm, offG_sm, offE_sm, lst, xs_sm, cand_sm, memlast_sm, pw_sm, s1_u32base); break;
    case 4: run_loop<4>(cl, lane, warp, b, i, ctile, xrow, orow, sW, beta, p, bb, inv_p,
                        s1_sm, masks, offS_sm, offG_sm, offE_sm, lst, xs_sm, cand_sm, memlast_sm, pw_sm, s1_u32base); break;
    case 5: run_loop<5>(cl, lane, warp, b, i, ctile, xrow, orow, sW, beta, p, bb, inv_p,
                        s1_sm, masks, offS_sm, offG_sm, offE_sm, lst, xs_sm, cand_sm, memlast_sm, pw_sm, s1_u32base); break;
    case 6: run_loop<6>(cl, lane, warp, b, i, ctile, xrow, orow, sW, beta, p, bb, inv_p,
                        s1_sm, masks, offS_sm, offG_sm, offE_sm, lst, xs_sm, cand_sm, memlast_sm, pw_sm, s1_u32base); break;
    default: run_loop<7>(cl, lane, warp, b, i, ctile, xrow, orow, sW, beta, p, bb, inv_p,
                        s1_sm, masks, offS_sm, offG_sm, offE_sm, lst, xs_sm, cand_sm, memlast_sm, pw_sm, s1_u32base); break;
    }
}

// ---------------------------------------------------------------------------
extern "C" void kernel_launch(void* const* d_in, const int* in_sizes, int n_in,
                              void* d_out, int out_size)
{
    const float* x        = (const float*)d_in[0];
    const float* beta_raw = (const float*)d_in[1];
    const float* rec_w    = (const float*)d_in[2];
    const float* p_raw    = (const float*)d_in[3];
    const float* b_raw    = (const float*)d_in[4];
    float* out = (float*)d_out;

    // opt-in to large dynamic smem (host-side attribute, not an allocation)
    static bool attr_set = false;
    if (!attr_set) {
        cudaFuncSetAttribute(snn_kernel,
                             cudaFuncAttributeMaxDynamicSharedMemorySize,
                             SW_BYTES);
        attr_set = true;
    }

    transpose_kernel<<<dim3(16, 16), dim3(32, 8)>>>(rec_w);
    // 148 CTAs (37 clusters of 4): clusters with b>=32 exit immediately
    snn_kernel<<<148, 1024, SW_BYTES>>>(x, beta_raw, p_raw, b_raw, out);
}